// round 16
// baseline (speedup 1.0000x reference)
#include <cuda_runtime.h>
#include <cuda_bf16.h>
#include <cstdint>

#define SB 8192   // B*S = 64*128

typedef unsigned long long ull;

// ---------------- device scratch ----------------
__device__ float4        g_P[300];             // [a=100][kk=3] -> float4 channels
__device__ __nv_bfloat16 g_xb[SB * 128];       // bf16 word embeddings, m = s*64+b
__device__ __nv_bfloat16 g_wihb[2048 * 128];   // bf16 Wih rows: [0,1024)=fwd, [1024,2048)=bwd
__device__ float  g_xz[2u * SB * 1024];        // x@Wih^T + b, [d][m][1024]
__device__ float4 g_Wp[2 * 256 * 256];         // packed Whh: [d][k][j] = (wi,wf,wg,wo)
__device__ float  g_h [2u * SB * 256];         // hidden states [d][m][256]
__device__ float  g_owT[512 * 64];             // out_w transposed [k][t]
__device__ float  g_tag[SB * 50];              // tag_space, m = b*128+s
__device__ float  g_hstep[16 * 2 * 256 * 8];   // per-group double-buffered h
__device__ unsigned g_bar[16];                 // per-group step counters

// ---------------- scalar helpers ----------------
__device__ __forceinline__ ull pk2(float a, float b) {
    ull r; asm("mov.b64 %0,{%1,%2};" : "=l"(r) : "f"(a), "f"(b)); return r;
}
__device__ __forceinline__ void up2(ull v, float& a, float& b) {
    asm("mov.b64 {%0,%1},%2;" : "=f"(a), "=f"(b) : "l"(v));
}
__device__ __forceinline__ ull ffma2(ull a, ull b, ull c) {
    ull d; asm("fma.rn.f32x2 %0,%1,%2,%3;" : "=l"(d) : "l"(a), "l"(b), "l"(c)); return d;
}
__device__ __forceinline__ ull addx2(ull a, ull b) {
    ull d; asm("add.rn.f32x2 %0,%1,%2;" : "=l"(d) : "l"(a), "l"(b)); return d;
}
__device__ __forceinline__ float sigf(float x) {
    return __fdividef(1.f, 1.f + __expf(-x));
}
__device__ __forceinline__ float tanhe(float x) {
    return 1.f - __fdividef(2.f, __expf(2.f * x) + 1.f);
}
__device__ __forceinline__ uint32_t smem_u32(const void* p) {
    uint32_t a;
    asm("{ .reg .u64 t; cvta.to.shared.u64 t, %1; cvt.u32.u64 %0, t; }" : "=r"(a) : "l"(p));
    return a;
}

// ---------------- HMMA helpers ----------------
__device__ __forceinline__ void ldm_x4(uint32_t* r, uint32_t a) {
    asm volatile("ldmatrix.sync.aligned.m8n8.x4.shared.b16 {%0,%1,%2,%3}, [%4];"
                 : "=r"(r[0]), "=r"(r[1]), "=r"(r[2]), "=r"(r[3]) : "r"(a));
}
__device__ __forceinline__ void ldm_x2(uint32_t* r, uint32_t a) {
    asm volatile("ldmatrix.sync.aligned.m8n8.x2.shared.b16 {%0,%1}, [%2];"
                 : "=r"(r[0]), "=r"(r[1]) : "r"(a));
}
__device__ __forceinline__ void mma16816(float* c, const uint32_t* a, const uint32_t* b) {
    asm volatile(
        "mma.sync.aligned.m16n8k16.row.col.f32.bf16.bf16.f32 "
        "{%0,%1,%2,%3},{%4,%5,%6,%7},{%8,%9},{%0,%1,%2,%3};"
        : "+f"(c[0]), "+f"(c[1]), "+f"(c[2]), "+f"(c[3])
        : "r"(a[0]), "r"(a[1]), "r"(a[2]), "r"(a[3]), "r"(b[0]), "r"(b[1]));
}

// ---------------- K_prep: fused pack + wihb + gatherb + outT + zero + ptab ----------------
// grid sections (5924 blocks x 256 thr):
//   [0,512)      pack Whh -> g_Wp
//   [512,1536)   Wih -> bf16
//   [1536,5632)  gather word emb -> bf16
//   [5632,5760)  out_w transpose
//   [5760,5824)  zero g_hstep + g_bar
//   [5824,5924)  char P table
#define PREP_BLOCKS 5924
__global__ void __launch_bounds__(256) k_prep(
    const float* __restrict__ whf, const float* __restrict__ whb,
    const float* __restrict__ wif, const float* __restrict__ wib,
    const int*   __restrict__ wids, const float* __restrict__ wemb,
    const float* __restrict__ ow,
    const float* __restrict__ cemb, const float* __restrict__ cw) {
    int bi = blockIdx.x, t = threadIdx.x;
    if (bi < 512) {
        int d = bi >> 8, k = bi & 255, j = t;
        const float* W = d ? whb : whf;              // [1024][256]
        float4 v;
        v.x = W[(0   + j) * 256 + k];
        v.y = W[(256 + j) * 256 + k];
        v.z = W[(512 + j) * 256 + k];
        v.w = W[(768 + j) * 256 + k];
        g_Wp[(size_t)d * 65536 + k * 256 + j] = v;
    } else if (bi < 1536) {
        int idx = (bi - 512) * 256 + t;              // 0..262143
        int n = idx >> 7, c = idx & 127;
        const float* src = (n < 1024) ? (wif + (size_t)n * 128)
                                      : (wib + (size_t)(n - 1024) * 128);
        g_wihb[(size_t)n * 128 + c] = __float2bfloat16_rn(src[c]);
    } else if (bi < 5632) {
        int idx = (bi - 1536) * 256 + t;             // 0..1048575
        int m = idx >> 7, c = idx & 127;
        int s = m >> 6, b = m & 63;
        int w = wids[b * 128 + s];
        g_xb[(size_t)m * 128 + c] = __float2bfloat16_rn(wemb[(size_t)w * 128 + c]);
    } else if (bi < 5760) {
        int idx = (bi - 5632) * 256 + t;             // 0..32767
        int k = idx >> 6, tt = idx & 63;
        g_owT[k * 64 + tt] = (tt < 50) ? ow[tt * 512 + k] : 0.f;
    } else if (bi < 5824) {
        int i = (bi - 5760) * 256 + t;               // 0..16383
        if (i < 16) g_bar[i] = 0u;
        float4 z = make_float4(0.f, 0.f, 0.f, 0.f);
        ((float4*)g_hstep)[i] = z;
    } else {
        int a = bi - 5824;                           // 0..99
        __shared__ float red[8];
        float ce = (t < 128) ? cemb[a * 128 + t] : 0.f;
        for (int p = 0; p < 12; p++) {
            int kk = p >> 2, c = p & 3;
            float v = (t < 128) ? ce * cw[c * 384 + kk * 128 + t] : 0.f;
            #pragma unroll
            for (int o = 16; o; o >>= 1) v += __shfl_xor_sync(0xffffffffu, v, o);
            if ((t & 31) == 0) red[t >> 5] = v;
            __syncthreads();
            if (t == 0)
                ((float*)g_P)[a * 12 + kk * 4 + c] = red[0] + red[1] + red[2] + red[3];
            __syncthreads();
        }
    }
}

// ---------------- K5: char CNN + maxpool -> tail of d_out ----------------
__global__ void k_char(const int* __restrict__ cid, const float* __restrict__ cb,
                       float* __restrict__ out) {
    __shared__ float4 P4[300];
    int tid = threadIdx.x;                           // 32 x 256
    for (int i = tid; i < 300; i += 256) P4[i] = g_P[i];
    __syncthreads();
    int m = blockIdx.x * 256 + tid;
    const int* ip = cid + (size_t)m * 18;
    int ids[18];
    #pragma unroll
    for (int i = 0; i < 18; i++) ids[i] = ip[i];
    float4 mx = make_float4(-1e30f, -1e30f, -1e30f, -1e30f);
    #pragma unroll
    for (int w = 0; w < 16; w++) {
        float4 A = P4[ids[w] * 3 + 0];
        float4 B = P4[ids[w + 1] * 3 + 1];
        float4 C = P4[ids[w + 2] * 3 + 2];
        mx.x = fmaxf(mx.x, A.x + B.x + C.x);
        mx.y = fmaxf(mx.y, A.y + B.y + C.y);
        mx.z = fmaxf(mx.z, A.z + B.z + C.z);
        mx.w = fmaxf(mx.w, A.w + B.w + C.w);
    }
    float4 o;
    o.x = mx.x + cb[0]; o.y = mx.y + cb[1]; o.z = mx.z + cb[2]; o.w = mx.w + cb[3];
    *(float4*)&out[409600 + (size_t)m * 4] = o;
}

// ---------------- K6: input GEMM via HMMA (validated 27us form) ----------------
#define HSM_STRIDE 136
#define HSM_BYTES  (2 * 128 * HSM_STRIDE * 2 + 512)   // 70144 B
extern __shared__ unsigned char hsm_raw[];
__global__ void __launch_bounds__(256) k_hmma(const float* __restrict__ bf,
                                              const float* __restrict__ bb) {
    __nv_bfloat16* As = (__nv_bfloat16*)hsm_raw;
    __nv_bfloat16* Bs = As + 128 * HSM_STRIDE;
    float* bsm = (float*)(Bs + 128 * HSM_STRIDE);
    int m0 = blockIdx.x * 128, n0 = blockIdx.y * 128;
    int t = threadIdx.x;

    #pragma unroll
    for (int i = t; i < 2048; i += 256) {
        int r = i >> 4, c8 = (i & 15) * 8;
        *(float4*)&As[r * HSM_STRIDE + c8] = *(const float4*)&g_xb[(size_t)(m0 + r) * 128 + c8];
        *(float4*)&Bs[r * HSM_STRIDE + c8] = *(const float4*)&g_wihb[(size_t)(n0 + r) * 128 + c8];
    }
    if (t < 128) {
        int n = n0 + t;
        bsm[t] = (n < 1024) ? bf[n] : bb[n - 1024];
    }
    __syncthreads();

    int w = t >> 5, lane = t & 31;
    int wm = (w >> 2) * 64, wn = (w & 3) * 32;   // 2m x 4n warps
    float acc[4][4][4] = {};
    #pragma unroll
    for (int kk = 0; kk < 8; kk++) {
        uint32_t a[4][4], b[4][2];
        #pragma unroll
        for (int mi = 0; mi < 4; mi++) {
            int row = wm + mi * 16 + (lane & 15);
            int col = kk * 16 + (lane >> 4) * 8;
            ldm_x4(a[mi], smem_u32(&As[row * HSM_STRIDE + col]));
        }
        #pragma unroll
        for (int nj = 0; nj < 4; nj++) {
            int row = wn + nj * 8 + (lane & 7);
            int col = kk * 16 + ((lane >> 3) & 1) * 8;
            ldm_x2(b[nj], smem_u32(&Bs[row * HSM_STRIDE + col]));
        }
        #pragma unroll
        for (int mi = 0; mi < 4; mi++)
            #pragma unroll
            for (int nj = 0; nj < 4; nj++)
                mma16816(acc[mi][nj], a[mi], b[nj]);
    }

    int d = n0 >> 10;
    int nb = n0 & 1023;
    #pragma unroll
    for (int mi = 0; mi < 4; mi++) {
        #pragma unroll
        for (int nj = 0; nj < 4; nj++) {
            int lrow = wm + mi * 16 + (lane >> 2);
            int lcol = wn + nj * 8 + (lane & 3) * 2;
            float b0 = bsm[lcol], b1 = bsm[lcol + 1];
            float2 v0 = make_float2(acc[mi][nj][0] + b0, acc[mi][nj][1] + b1);
            float2 v1 = make_float2(acc[mi][nj][2] + b0, acc[mi][nj][3] + b1);
            size_t base = ((size_t)d * SB + m0 + lrow) * 1024 + nb + lcol;
            *(float2*)&g_xz[base]             = v0;
            *(float2*)&g_xz[base + 8 * 1024]  = v1;
        }
    }
}

// ---------------- K7: BiLSTM recurrence (R6 champion form, byte-identical) ----------------
extern __shared__ unsigned char sm_raw[];
__global__ void __launch_bounds__(256, 1) k_lstm2() {
    int bx  = blockIdx.x;
    int dir = bx >> 6;
    int g   = bx >> 3;
    int grp = (bx >> 3) & 7;
    int js  = bx & 7;
    int t   = threadIdx.x;
    int b0  = grp * 8;

    ulonglong2* Wsm = (ulonglong2*)sm_raw;                       // [256*32]
    ull*        hs2 = (ull*)(sm_raw + 131072);                   // [256*8]
    ulonglong2* red = (ulonglong2*)(sm_raw + 131072 + 16384);    // [8][32][9]

    for (int i = t; i < 256 * 32; i += 256) {
        int k = i >> 5, jl = i & 31;
        float4 w = g_Wp[(size_t)dir * 65536 + k * 256 + js * 32 + jl];
        ulonglong2 v; v.x = pk2(w.x, w.y); v.y = pk2(w.z, w.w);
        Wsm[i] = v;
    }
    __syncthreads();

    int ks = t >> 5, jl = t & 31;
    int br = t >> 5, jr = t & 31;
    int jglob = js * 32 + jr;
    float cc = 0.f;

    const ulonglong2* Wp2 = Wsm + ks * 1024 + jl;
    const ulonglong2* hpb = (const ulonglong2*)hs2 + ks * 128;

    for (int it = 0; it < 128; it++) {
        int s = dir ? (127 - it) : it;
        int p = it & 1;

        const float* xzp = g_xz + ((size_t)dir * SB + (size_t)s * 64 + b0 + br) * 1024 + jglob;
        float xi = xzp[0], xf = xzp[256], xg = xzp[512], xo = xzp[768];

        {
            const float4* src = (const float4*)(g_hstep + (g * 2 + p) * 2048) + t * 2;
            float4 a = src[0], b4 = src[1];
            ulonglong2* dst = (ulonglong2*)(hs2 + t * 8);
            ulonglong2 v0, v1, v2, v3;
            v0.x = pk2(a.x, a.x);  v0.y = pk2(a.y, a.y);
            v1.x = pk2(a.z, a.z);  v1.y = pk2(a.w, a.w);
            v2.x = pk2(b4.x, b4.x); v2.y = pk2(b4.y, b4.y);
            v3.x = pk2(b4.z, b4.z); v3.y = pk2(b4.w, b4.w);
            dst[0] = v0; dst[1] = v1; dst[2] = v2; dst[3] = v3;
        }
        __syncthreads();

        ull aif[8], ago[8];
        #pragma unroll
        for (int b = 0; b < 8; b++) { aif[b] = 0ull; ago[b] = 0ull; }
        #pragma unroll 4
        for (int kk = 0; kk < 32; kk++) {
            ulonglong2 wv = Wp2[kk * 32];
            ulonglong2 p0 = hpb[kk * 4 + 0], p1 = hpb[kk * 4 + 1];
            ulonglong2 p2 = hpb[kk * 4 + 2], p3 = hpb[kk * 4 + 3];
            aif[0] = ffma2(wv.x, p0.x, aif[0]); ago[0] = ffma2(wv.y, p0.x, ago[0]);
            aif[1] = ffma2(wv.x, p0.y, aif[1]); ago[1] = ffma2(wv.y, p0.y, ago[1]);
            aif[2] = ffma2(wv.x, p1.x, aif[2]); ago[2] = ffma2(wv.y, p1.x, ago[2]);
            aif[3] = ffma2(wv.x, p1.y, aif[3]); ago[3] = ffma2(wv.y, p1.y, ago[3]);
            aif[4] = ffma2(wv.x, p2.x, aif[4]); ago[4] = ffma2(wv.y, p2.x, ago[4]);
            aif[5] = ffma2(wv.x, p2.y, aif[5]); ago[5] = ffma2(wv.y, p2.y, ago[5]);
            aif[6] = ffma2(wv.x, p3.x, aif[6]); ago[6] = ffma2(wv.y, p3.x, ago[6]);
            aif[7] = ffma2(wv.x, p3.y, aif[7]); ago[7] = ffma2(wv.y, p3.y, ago[7]);
        }
        #pragma unroll
        for (int b = 0; b < 8; b++) {
            ulonglong2 v; v.x = aif[b]; v.y = ago[b];
            red[(b * 32 + jl) * 9 + ks] = v;
        }
        __syncthreads();

        ull sa = 0ull, sg = 0ull;
        const ulonglong2* rr = red + (br * 32 + jr) * 9;
        #pragma unroll
        for (int q = 0; q < 8; q++) {
            ulonglong2 v = rr[q];
            sa = addx2(sa, v.x); sg = addx2(sg, v.y);
        }
        float zi, zf, zg, zo;
        up2(sa, zi, zf); up2(sg, zg, zo);
        zi += xi; zf += xf; zg += xg; zo += xo;
        cc = sigf(zf) * cc + sigf(zi) * tanhe(zg);
        float hv = sigf(zo) * tanhe(cc);
        g_hstep[(g * 2 + (p ^ 1)) * 2048 + jglob * 8 + br] = hv;
        g_h[((size_t)dir * SB + (size_t)s * 64 + b0 + br) * 256 + jglob] = hv;
        __syncthreads();

        if (t == 0) {
            __threadfence();
            atomicAdd(&g_bar[g], 1u);
            unsigned tgt = 8u * (unsigned)(it + 1), v;
            do {
                asm volatile("ld.global.acquire.gpu.u32 %0,[%1];" : "=r"(v) : "l"(&g_bar[g]));
                if (v < tgt) __nanosleep(64);
            } while (v < tgt);
        }
        __syncthreads();
    }
}

// ---------------- K8: output layer ----------------
__global__ void __launch_bounds__(256) k_out(const float* __restrict__ outb) {
    __shared__ float hs[16][516];
    int mo0 = blockIdx.x * 16;              // 512 blocks
    int b = mo0 >> 7, s0 = mo0 & 127;
    int tid = threadIdx.x;
    #pragma unroll
    for (int i = 0; i < 8; i++) {
        int fi = tid + i * 256;
        int row = fi >> 7, c4 = fi & 127;
        int ms = (s0 + row) * 64 + b;
        const float* src = (c4 < 64)
            ? &g_h[((size_t)0 * SB + ms) * 256 + c4 * 4]
            : &g_h[((size_t)1 * SB + ms) * 256 + (c4 - 64) * 4];
        *(float4*)&hs[row][c4 * 4] = *(const float4*)src;
    }
    __syncthreads();
    int tt = tid & 63, mg = tid >> 6;
    float acc[4] = {0.f, 0.f, 0.f, 0.f};
    #pragma unroll 4
    for (int k = 0; k < 512; k++) {
        float w = g_owT[k * 64 + tt];
        #pragma unroll
        for (int r = 0; r < 4; r++) acc[r] += hs[mg * 4 + r][k] * w;
    }
    if (tt < 50) {
        float bb = outb[tt];
        #pragma unroll
        for (int r = 0; r < 4; r++)
            g_tag[(size_t)(mo0 + mg * 4 + r) * 50 + tt] = acc[r] + bb;
    }
}

// ---------------- K9: log_softmax over seq axis (smem-cached, 256 thr) ----------------
__global__ void __launch_bounds__(256) k_lsm(float* __restrict__ out) {
    __shared__ float tg[128][52];
    __shared__ float r4[4][64];
    __shared__ float lse[64];
    int b = blockIdx.x, t = threadIdx.x;    // 64 blocks x 256 threads
    const float* src = g_tag + (size_t)b * 6400;
    for (int i = t; i < 6400; i += 256) tg[i / 50][i % 50] = src[i];
    __syncthreads();
    int tt = t & 63, q = t >> 6;
    float mx = -1e30f;
    if (tt < 50) {
        #pragma unroll 4
        for (int s = q * 32; s < q * 32 + 32; s++) mx = fmaxf(mx, tg[s][tt]);
    }
    r4[q][tt] = mx;
    __syncthreads();
    if (q == 0 && tt < 50)
        lse[tt] = fmaxf(fmaxf(r4[0][tt], r4[1][tt]), fmaxf(r4[2][tt], r4[3][tt]));
    __syncthreads();
    float m = lse[tt < 50 ? tt : 0];
    float sum = 0.f;
    if (tt < 50) {
        #pragma unroll 4
        for (int s = q * 32; s < q * 32 + 32; s++) sum += __expf(tg[s][tt] - m);
    }
    r4[q][tt] = sum;
    __syncthreads();
    if (q == 0 && tt < 50)
        lse[tt] = m + __logf(r4[0][tt] + r4[1][tt] + r4[2][tt] + r4[3][tt]);
    __syncthreads();
    float* ob = out + (size_t)b * 6400;
    for (int i = t; i < 6400; i += 256) ob[i] = tg[i / 50][i % 50] - lse[i % 50];
}

// ---------------- launcher ----------------
extern "C" void kernel_launch(void* const* d_in, const int* in_sizes, int n_in,
                              void* d_out, int out_size) {
    const int*   char_ids = (const int*)  d_in[0];
    const int*   word_ids = (const int*)  d_in[1];
    const float* char_emb = (const float*)d_in[2];
    const float* word_emb = (const float*)d_in[3];
    const float* cnn_w    = (const float*)d_in[4];
    const float* cnn_b    = (const float*)d_in[5];
    const float* wih_f    = (const float*)d_in[6];
    const float* whh_f    = (const float*)d_in[7];
    const float* b_f      = (const float*)d_in[8];
    const float* wih_b    = (const float*)d_in[9];
    const float* whh_b    = (const float*)d_in[10];
    const float* b_b      = (const float*)d_in[11];
    const float* out_w    = (const float*)d_in[12];
    const float* out_b    = (const float*)d_in[13];
    float* out = (float*)d_out;

    // unconditional, idempotent (no static guards allowed)
    cudaFuncSetAttribute(k_lstm2, cudaFuncAttributeMaxDynamicSharedMemorySize, 184320);
    cudaFuncSetAttribute(k_hmma,  cudaFuncAttributeMaxDynamicSharedMemorySize, HSM_BYTES);

    k_prep <<<PREP_BLOCKS, 256>>>(whh_f, whh_b, wih_f, wih_b,
                                  word_ids, word_emb, out_w, char_emb, cnn_w); // 0
    k_hmma <<<dim3(64, 16), 256, HSM_BYTES>>>(b_f, b_b);                       // 1
    k_lstm2<<<128, 256, 184320>>>();                                           // 2
    k_char <<<32,  256>>>(char_ids, cnn_b, out);                               // 3
    k_out  <<<512, 256>>>(out_b);                                              // 4
    k_lsm  <<<64,  256>>>(out);                                                // 5
}

// round 17
// speedup vs baseline: 1.0309x; 1.0309x over previous
#include <cuda_runtime.h>
#include <cuda_bf16.h>
#include <cstdint>

#define SB 8192   // B*S = 64*128

typedef unsigned long long ull;

// ---------------- device scratch ----------------
__device__ float4        g_P[300];             // [a=100][kk=3] -> float4 channels
__device__ __nv_bfloat16 g_xb[SB * 128];       // bf16 word embeddings, m = s*64+b
__device__ __nv_bfloat16 g_wihb[2048 * 128];   // bf16 Wih rows: [0,1024)=fwd, [1024,2048)=bwd
__device__ float  g_xz[2u * SB * 1024];        // x@Wih^T + b, [d][m][1024]
__device__ float4 g_Wp[2 * 256 * 256];         // packed Whh: [d][k][j] = (wi,wf,wg,wo)
__device__ float  g_h [2u * SB * 256];         // hidden states [d][m][256]
__device__ float  g_owT[512 * 64];             // out_w transposed [k][t]
__device__ float  g_tag[SB * 50];              // tag_space, m = b*128+s
__device__ float  g_hstep[16 * 2 * 256 * 8];   // per-group double-buffered h
__device__ unsigned g_bar[16 * 32];            // per-group step counters, 1 per 128B line

// ---------------- scalar helpers ----------------
__device__ __forceinline__ ull pk2(float a, float b) {
    ull r; asm("mov.b64 %0,{%1,%2};" : "=l"(r) : "f"(a), "f"(b)); return r;
}
__device__ __forceinline__ void up2(ull v, float& a, float& b) {
    asm("mov.b64 {%0,%1},%2;" : "=f"(a), "=f"(b) : "l"(v));
}
__device__ __forceinline__ ull ffma2(ull a, ull b, ull c) {
    ull d; asm("fma.rn.f32x2 %0,%1,%2,%3;" : "=l"(d) : "l"(a), "l"(b), "l"(c)); return d;
}
__device__ __forceinline__ ull addx2(ull a, ull b) {
    ull d; asm("add.rn.f32x2 %0,%1,%2;" : "=l"(d) : "l"(a), "l"(b)); return d;
}
__device__ __forceinline__ float sigf(float x) {
    return __fdividef(1.f, 1.f + __expf(-x));
}
__device__ __forceinline__ float tanhe(float x) {
    return 1.f - __fdividef(2.f, __expf(2.f * x) + 1.f);
}
__device__ __forceinline__ uint32_t smem_u32(const void* p) {
    uint32_t a;
    asm("{ .reg .u64 t; cvta.to.shared.u64 t, %1; cvt.u32.u64 %0, t; }" : "=r"(a) : "l"(p));
    return a;
}

// ---------------- HMMA helpers ----------------
__device__ __forceinline__ void ldm_x4(uint32_t* r, uint32_t a) {
    asm volatile("ldmatrix.sync.aligned.m8n8.x4.shared.b16 {%0,%1,%2,%3}, [%4];"
                 : "=r"(r[0]), "=r"(r[1]), "=r"(r[2]), "=r"(r[3]) : "r"(a));
}
__device__ __forceinline__ void ldm_x2(uint32_t* r, uint32_t a) {
    asm volatile("ldmatrix.sync.aligned.m8n8.x2.shared.b16 {%0,%1}, [%2];"
                 : "=r"(r[0]), "=r"(r[1]) : "r"(a));
}
__device__ __forceinline__ void mma16816(float* c, const uint32_t* a, const uint32_t* b) {
    asm volatile(
        "mma.sync.aligned.m16n8k16.row.col.f32.bf16.bf16.f32 "
        "{%0,%1,%2,%3},{%4,%5,%6,%7},{%8,%9},{%0,%1,%2,%3};"
        : "+f"(c[0]), "+f"(c[1]), "+f"(c[2]), "+f"(c[3])
        : "r"(a[0]), "r"(a[1]), "r"(a[2]), "r"(a[3]), "r"(b[0]), "r"(b[1]));
}

// ---------------- K1: P table ----------------
__global__ void k_ptab(const float* __restrict__ cemb, const float* __restrict__ cw) {
    int a = blockIdx.x, t = threadIdx.x;     // 100 x 128
    float ce = cemb[a * 128 + t];
    __shared__ float red[4];
    for (int p = 0; p < 12; p++) {
        int kk = p >> 2, c = p & 3;
        float v = ce * cw[c * 384 + kk * 128 + t];
        #pragma unroll
        for (int o = 16; o; o >>= 1) v += __shfl_xor_sync(0xffffffffu, v, o);
        if ((t & 31) == 0) red[t >> 5] = v;
        __syncthreads();
        if (t == 0) ((float*)g_P)[a * 12 + kk * 4 + c] = red[0] + red[1] + red[2] + red[3];
        __syncthreads();
    }
}

// ---------------- K2: pack Whh -> [d][k][j] float4 ----------------
__global__ void k_pack(const float* __restrict__ wf, const float* __restrict__ wb) {
    int d = blockIdx.x >> 8, k = blockIdx.x & 255;   // 512 x 256
    int j = threadIdx.x;
    const float* W = d ? wb : wf;                    // [1024][256]
    float4 v;
    v.x = W[(0   + j) * 256 + k];
    v.y = W[(256 + j) * 256 + k];
    v.z = W[(512 + j) * 256 + k];
    v.w = W[(768 + j) * 256 + k];
    g_Wp[(size_t)d * 65536 + k * 256 + j] = v;
}

// ---------------- K3: Wih -> bf16 [2048][128] ----------------
__global__ void k_wihb(const float* __restrict__ wf, const float* __restrict__ wb) {
    int n = blockIdx.x, t = threadIdx.x;             // 2048 x 128
    const float* src = (n < 1024) ? (wf + (size_t)n * 128) : (wb + (size_t)(n - 1024) * 128);
    g_wihb[(size_t)n * 128 + t] = __float2bfloat16_rn(src[t]);
}

// ---------------- K4: gather word embeddings -> bf16 ----------------
__global__ void k_gatherb(const int* __restrict__ wids, const float* __restrict__ wemb) {
    int m = blockIdx.x, t = threadIdx.x;             // 8192 x 128
    int s = m >> 6, b = m & 63;
    int w = wids[b * 128 + s];
    g_xb[(size_t)m * 128 + t] = __float2bfloat16_rn(wemb[(size_t)w * 128 + t]);
}

// ---------------- K3b: transpose out_w ----------------
__global__ void k_outT(const float* __restrict__ ow) {
    int k = blockIdx.x, t = threadIdx.x;             // 512 x 64
    g_owT[k * 64 + t] = (t < 50) ? ow[t * 512 + k] : 0.f;
}

// ---------------- K5: char CNN + maxpool -> tail of d_out ----------------
__global__ void k_char(const int* __restrict__ cid, const float* __restrict__ cb,
                       float* __restrict__ out) {
    __shared__ float4 P4[300];
    int tid = threadIdx.x;                           // 32 x 256
    for (int i = tid; i < 300; i += 256) P4[i] = g_P[i];
    __syncthreads();
    int m = blockIdx.x * 256 + tid;
    const int* ip = cid + (size_t)m * 18;
    int ids[18];
    #pragma unroll
    for (int i = 0; i < 18; i++) ids[i] = ip[i];
    float4 mx = make_float4(-1e30f, -1e30f, -1e30f, -1e30f);
    #pragma unroll
    for (int w = 0; w < 16; w++) {
        float4 A = P4[ids[w] * 3 + 0];
        float4 B = P4[ids[w + 1] * 3 + 1];
        float4 C = P4[ids[w + 2] * 3 + 2];
        mx.x = fmaxf(mx.x, A.x + B.x + C.x);
        mx.y = fmaxf(mx.y, A.y + B.y + C.y);
        mx.z = fmaxf(mx.z, A.z + B.z + C.z);
        mx.w = fmaxf(mx.w, A.w + B.w + C.w);
    }
    float4 o;
    o.x = mx.x + cb[0]; o.y = mx.y + cb[1]; o.z = mx.z + cb[2]; o.w = mx.w + cb[3];
    *(float4*)&out[409600 + (size_t)m * 4] = o;
}

// ---------------- K6: input GEMM via HMMA (validated 27us form) ----------------
#define HSM_STRIDE 136
#define HSM_BYTES  (2 * 128 * HSM_STRIDE * 2 + 512)   // 70144 B
extern __shared__ unsigned char hsm_raw[];
__global__ void __launch_bounds__(256) k_hmma(const float* __restrict__ bf,
                                              const float* __restrict__ bb) {
    __nv_bfloat16* As = (__nv_bfloat16*)hsm_raw;
    __nv_bfloat16* Bs = As + 128 * HSM_STRIDE;
    float* bsm = (float*)(Bs + 128 * HSM_STRIDE);
    int m0 = blockIdx.x * 128, n0 = blockIdx.y * 128;
    int t = threadIdx.x;

    #pragma unroll
    for (int i = t; i < 2048; i += 256) {
        int r = i >> 4, c8 = (i & 15) * 8;
        *(float4*)&As[r * HSM_STRIDE + c8] = *(const float4*)&g_xb[(size_t)(m0 + r) * 128 + c8];
        *(float4*)&Bs[r * HSM_STRIDE + c8] = *(const float4*)&g_wihb[(size_t)(n0 + r) * 128 + c8];
    }
    if (t < 128) {
        int n = n0 + t;
        bsm[t] = (n < 1024) ? bf[n] : bb[n - 1024];
    }
    __syncthreads();

    int w = t >> 5, lane = t & 31;
    int wm = (w >> 2) * 64, wn = (w & 3) * 32;   // 2m x 4n warps
    float acc[4][4][4] = {};
    #pragma unroll
    for (int kk = 0; kk < 8; kk++) {
        uint32_t a[4][4], b[4][2];
        #pragma unroll
        for (int mi = 0; mi < 4; mi++) {
            int row = wm + mi * 16 + (lane & 15);
            int col = kk * 16 + (lane >> 4) * 8;
            ldm_x4(a[mi], smem_u32(&As[row * HSM_STRIDE + col]));
        }
        #pragma unroll
        for (int nj = 0; nj < 4; nj++) {
            int row = wn + nj * 8 + (lane & 7);
            int col = kk * 16 + ((lane >> 3) & 1) * 8;
            ldm_x2(b[nj], smem_u32(&Bs[row * HSM_STRIDE + col]));
        }
        #pragma unroll
        for (int mi = 0; mi < 4; mi++)
            #pragma unroll
            for (int nj = 0; nj < 4; nj++)
                mma16816(acc[mi][nj], a[mi], b[nj]);
    }

    int d = n0 >> 10;
    int nb = n0 & 1023;
    #pragma unroll
    for (int mi = 0; mi < 4; mi++) {
        #pragma unroll
        for (int nj = 0; nj < 4; nj++) {
            int lrow = wm + mi * 16 + (lane >> 2);
            int lcol = wn + nj * 8 + (lane & 3) * 2;
            float b0 = bsm[lcol], b1 = bsm[lcol + 1];
            float2 v0 = make_float2(acc[mi][nj][0] + b0, acc[mi][nj][1] + b1);
            float2 v1 = make_float2(acc[mi][nj][2] + b0, acc[mi][nj][3] + b1);
            size_t base = ((size_t)d * SB + m0 + lrow) * 1024 + nb + lcol;
            *(float2*)&g_xz[base]             = v0;
            *(float2*)&g_xz[base + 8 * 1024]  = v1;
        }
    }
}

// ---------------- K0: zero step buffers + barriers ----------------
__global__ void k_zero() {
    int i = blockIdx.x * 256 + threadIdx.x;          // 64 x 256 = 16384
    if (i < 512) g_bar[i] = 0u;
    float4 z = make_float4(0.f, 0.f, 0.f, 0.f);
    ((float4*)g_hstep)[i] = z;
}

// ---------------- K7: BiLSTM recurrence (champion form; barrier counters padded) ----
// 128 blocks = 2 dir x 8 batch-groups x 8 j-slices, single wave (1 blk/SM).
// g_bar stride 32 (128B): each group's release+poll owns a private L2 line,
// eliminating cross-group false sharing on the counter line.
extern __shared__ unsigned char sm_raw[];
__global__ void __launch_bounds__(256, 1) k_lstm2() {
    int bx  = blockIdx.x;
    int dir = bx >> 6;
    int g   = bx >> 3;
    int grp = (bx >> 3) & 7;
    int js  = bx & 7;
    int t   = threadIdx.x;
    int b0  = grp * 8;
    unsigned* barp = &g_bar[g * 32];

    ulonglong2* Wsm = (ulonglong2*)sm_raw;                       // [256*32]
    ull*        hs2 = (ull*)(sm_raw + 131072);                   // [256*8]
    ulonglong2* red = (ulonglong2*)(sm_raw + 131072 + 16384);    // [8][32][9]

    for (int i = t; i < 256 * 32; i += 256) {
        int k = i >> 5, jl = i & 31;
        float4 w = g_Wp[(size_t)dir * 65536 + k * 256 + js * 32 + jl];
        ulonglong2 v; v.x = pk2(w.x, w.y); v.y = pk2(w.z, w.w);
        Wsm[i] = v;
    }
    __syncthreads();

    int ks = t >> 5, jl = t & 31;
    int br = t >> 5, jr = t & 31;
    int jglob = js * 32 + jr;
    float cc = 0.f;

    const ulonglong2* Wp2 = Wsm + ks * 1024 + jl;
    const ulonglong2* hpb = (const ulonglong2*)hs2 + ks * 128;

    for (int it = 0; it < 128; it++) {
        int s = dir ? (127 - it) : it;
        int p = it & 1;

        const float* xzp = g_xz + ((size_t)dir * SB + (size_t)s * 64 + b0 + br) * 1024 + jglob;
        float xi = xzp[0], xf = xzp[256], xg = xzp[512], xo = xzp[768];

        {
            const float4* src = (const float4*)(g_hstep + (g * 2 + p) * 2048) + t * 2;
            float4 a = src[0], b4 = src[1];
            ulonglong2* dst = (ulonglong2*)(hs2 + t * 8);
            ulonglong2 v0, v1, v2, v3;
            v0.x = pk2(a.x, a.x);  v0.y = pk2(a.y, a.y);
            v1.x = pk2(a.z, a.z);  v1.y = pk2(a.w, a.w);
            v2.x = pk2(b4.x, b4.x); v2.y = pk2(b4.y, b4.y);
            v3.x = pk2(b4.z, b4.z); v3.y = pk2(b4.w, b4.w);
            dst[0] = v0; dst[1] = v1; dst[2] = v2; dst[3] = v3;
        }
        __syncthreads();

        ull aif[8], ago[8];
        #pragma unroll
        for (int b = 0; b < 8; b++) { aif[b] = 0ull; ago[b] = 0ull; }
        #pragma unroll 4
        for (int kk = 0; kk < 32; kk++) {
            ulonglong2 wv = Wp2[kk * 32];
            ulonglong2 p0 = hpb[kk * 4 + 0], p1 = hpb[kk * 4 + 1];
            ulonglong2 p2 = hpb[kk * 4 + 2], p3 = hpb[kk * 4 + 3];
            aif[0] = ffma2(wv.x, p0.x, aif[0]); ago[0] = ffma2(wv.y, p0.x, ago[0]);
            aif[1] = ffma2(wv.x, p0.y, aif[1]); ago[1] = ffma2(wv.y, p0.y, ago[1]);
            aif[2] = ffma2(wv.x, p1.x, aif[2]); ago[2] = ffma2(wv.y, p1.x, ago[2]);
            aif[3] = ffma2(wv.x, p1.y, aif[3]); ago[3] = ffma2(wv.y, p1.y, ago[3]);
            aif[4] = ffma2(wv.x, p2.x, aif[4]); ago[4] = ffma2(wv.y, p2.x, ago[4]);
            aif[5] = ffma2(wv.x, p2.y, aif[5]); ago[5] = ffma2(wv.y, p2.y, ago[5]);
            aif[6] = ffma2(wv.x, p3.x, aif[6]); ago[6] = ffma2(wv.y, p3.x, ago[6]);
            aif[7] = ffma2(wv.x, p3.y, aif[7]); ago[7] = ffma2(wv.y, p3.y, ago[7]);
        }
        #pragma unroll
        for (int b = 0; b < 8; b++) {
            ulonglong2 v; v.x = aif[b]; v.y = ago[b];
            red[(b * 32 + jl) * 9 + ks] = v;
        }
        __syncthreads();

        ull sa = 0ull, sg = 0ull;
        const ulonglong2* rr = red + (br * 32 + jr) * 9;
        #pragma unroll
        for (int q = 0; q < 8; q++) {
            ulonglong2 v = rr[q];
            sa = addx2(sa, v.x); sg = addx2(sg, v.y);
        }
        float zi, zf, zg, zo;
        up2(sa, zi, zf); up2(sg, zg, zo);
        zi += xi; zf += xf; zg += xg; zo += xo;
        cc = sigf(zf) * cc + sigf(zi) * tanhe(zg);
        float hv = sigf(zo) * tanhe(cc);
        g_hstep[(g * 2 + (p ^ 1)) * 2048 + jglob * 8 + br] = hv;
        g_h[((size_t)dir * SB + (size_t)s * 64 + b0 + br) * 256 + jglob] = hv;
        __syncthreads();

        if (t == 0) {
            __threadfence();
            atomicAdd(barp, 1u);
            unsigned tgt = 8u * (unsigned)(it + 1), v;
            do {
                asm volatile("ld.global.acquire.gpu.u32 %0,[%1];" : "=r"(v) : "l"(barp));
                if (v < tgt) __nanosleep(64);
            } while (v < tgt);
        }
        __syncthreads();
    }
}

// ---------------- K8: output layer ----------------
__global__ void __launch_bounds__(256) k_out(const float* __restrict__ outb) {
    __shared__ float hs[16][516];
    int mo0 = blockIdx.x * 16;              // 512 blocks
    int b = mo0 >> 7, s0 = mo0 & 127;
    int tid = threadIdx.x;
    #pragma unroll
    for (int i = 0; i < 8; i++) {
        int fi = tid + i * 256;
        int row = fi >> 7, c4 = fi & 127;
        int ms = (s0 + row) * 64 + b;
        const float* src = (c4 < 64)
            ? &g_h[((size_t)0 * SB + ms) * 256 + c4 * 4]
            : &g_h[((size_t)1 * SB + ms) * 256 + (c4 - 64) * 4];
        *(float4*)&hs[row][c4 * 4] = *(const float4*)src;
    }
    __syncthreads();
    int tt = tid & 63, mg = tid >> 6;
    float acc[4] = {0.f, 0.f, 0.f, 0.f};
    #pragma unroll 4
    for (int k = 0; k < 512; k++) {
        float w = g_owT[k * 64 + tt];
        #pragma unroll
        for (int r = 0; r < 4; r++) acc[r] += hs[mg * 4 + r][k] * w;
    }
    if (tt < 50) {
        float bb = outb[tt];
        #pragma unroll
        for (int r = 0; r < 4; r++)
            g_tag[(size_t)(mo0 + mg * 4 + r) * 50 + tt] = acc[r] + bb;
    }
}

// ---------------- K9: log_softmax over seq axis (smem-cached, 256 thr) ----------------
__global__ void __launch_bounds__(256) k_lsm(float* __restrict__ out) {
    __shared__ float tg[128][52];
    __shared__ float r4[4][64];
    __shared__ float lse[64];
    int b = blockIdx.x, t = threadIdx.x;    // 64 blocks x 256 threads
    const float* src = g_tag + (size_t)b * 6400;
    for (int i = t; i < 6400; i += 256) tg[i / 50][i % 50] = src[i];
    __syncthreads();
    int tt = t & 63, q = t >> 6;
    float mx = -1e30f;
    if (tt < 50) {
        #pragma unroll 4
        for (int s = q * 32; s < q * 32 + 32; s++) mx = fmaxf(mx, tg[s][tt]);
    }
    r4[q][tt] = mx;
    __syncthreads();
    if (q == 0 && tt < 50)
        lse[tt] = fmaxf(fmaxf(r4[0][tt], r4[1][tt]), fmaxf(r4[2][tt], r4[3][tt]));
    __syncthreads();
    float m = lse[tt < 50 ? tt : 0];
    float sum = 0.f;
    if (tt < 50) {
        #pragma unroll 4
        for (int s = q * 32; s < q * 32 + 32; s++) sum += __expf(tg[s][tt] - m);
    }
    r4[q][tt] = sum;
    __syncthreads();
    if (q == 0 && tt < 50)
        lse[tt] = m + __logf(r4[0][tt] + r4[1][tt] + r4[2][tt] + r4[3][tt]);
    __syncthreads();
    float* ob = out + (size_t)b * 6400;
    for (int i = t; i < 6400; i += 256) ob[i] = tg[i / 50][i % 50] - lse[i % 50];
}

// ---------------- launcher ----------------
extern "C" void kernel_launch(void* const* d_in, const int* in_sizes, int n_in,
                              void* d_out, int out_size) {
    const int*   char_ids = (const int*)  d_in[0];
    const int*   word_ids = (const int*)  d_in[1];
    const float* char_emb = (const float*)d_in[2];
    const float* word_emb = (const float*)d_in[3];
    const float* cnn_w    = (const float*)d_in[4];
    const float* cnn_b    = (const float*)d_in[5];
    const float* wih_f    = (const float*)d_in[6];
    const float* whh_f    = (const float*)d_in[7];
    const float* b_f      = (const float*)d_in[8];
    const float* wih_b    = (const float*)d_in[9];
    const float* whh_b    = (const float*)d_in[10];
    const float* b_b      = (const float*)d_in[11];
    const float* out_w    = (const float*)d_in[12];
    const float* out_b    = (const float*)d_in[13];
    float* out = (float*)d_out;

    // unconditional, idempotent (no static guards allowed)
    cudaFuncSetAttribute(k_lstm2, cudaFuncAttributeMaxDynamicSharedMemorySize, 184320);
    cudaFuncSetAttribute(k_hmma,  cudaFuncAttributeMaxDynamicSharedMemorySize, HSM_BYTES);

    // k_lstm2 is launch index 5 (ncu -s 5 -c 1 captures it)
    k_pack   <<<512, 256>>>(whh_f, whh_b);                        // 0
    k_wihb   <<<2048, 128>>>(wih_f, wih_b);                       // 1
    k_gatherb<<<8192, 128>>>(word_ids, word_emb);                 // 2
    k_hmma   <<<dim3(64, 16), 256, HSM_BYTES>>>(b_f, b_b);        // 3
    k_zero   <<<64, 256>>>();                                     // 4
    k_lstm2  <<<128, 256, 184320>>>();                            // 5
    k_ptab   <<<100, 128>>>(char_emb, cnn_w);                     // 6
    k_char   <<<32,  256>>>(char_ids, cnn_b, out);                // 7
    k_outT   <<<512,  64>>>(out_w);                               // 8
    k_out    <<<512, 256>>>(out_b);                               // 9
    k_lsm    <<<64,  256>>>(out);                                 // 10
}